// round 17
// baseline (speedup 1.0000x reference)
#include <cuda_runtime.h>
#include <cuda_fp16.h>
#include <cstdint>
#include <math.h>

#define Bq 2
#define Lq 2048
#define Dq 1024
#define Hq 16
#define HDq 64
#define HALFW 128
#define QT 128

// Scratch (no cudaMalloc allowed)
__device__ __half g_qkv16[(size_t)Bq * Lq * 3 * Dq];  // [B,L,3,D] single fp16
__device__ __half g_x_h[(size_t)Bq * Lq * Dq];
__device__ __half g_wqkv_h[(size_t)Dq * 3 * Dq];
__device__ __half g_wout_h[(size_t)Dq * Dq];
__device__ __half g_attn_h[(size_t)Bq * Lq * Dq];

// ===========================================================================
// helpers
// ===========================================================================
__device__ __forceinline__ uint16_t f16_of(float x) {
    return __half_raw(__float2half_rn(x)).x;
}

__device__ __forceinline__ uint32_t pack2(uint16_t a, uint16_t b) {
    return (uint32_t)a | ((uint32_t)b << 16);
}

__device__ __forceinline__ uint32_t f16x2_of(float flo, float fhi) {
    uint32_t r;
    asm("cvt.rn.f16x2.f32 %0, %1, %2;" : "=r"(r) : "f"(fhi), "f"(flo));
    return r;
}

__device__ __forceinline__ uint32_t smem_u32(const void* p) {
    uint32_t a;
    asm("{ .reg .u64 t; cvta.to.shared.u64 t, %1; cvt.u32.u64 %0, t; }" : "=r"(a) : "l"(p));
    return a;
}

__device__ __forceinline__ void ldm_x4(uint32_t& r0, uint32_t& r1, uint32_t& r2, uint32_t& r3,
                                       uint32_t addr) {
    asm volatile("ldmatrix.sync.aligned.m8n8.x4.shared.b16 {%0,%1,%2,%3}, [%4];"
                 : "=r"(r0), "=r"(r1), "=r"(r2), "=r"(r3) : "r"(addr));
}
__device__ __forceinline__ void ldm_x4_t(uint32_t& r0, uint32_t& r1, uint32_t& r2, uint32_t& r3,
                                         uint32_t addr) {
    asm volatile("ldmatrix.sync.aligned.m8n8.x4.trans.shared.b16 {%0,%1,%2,%3}, [%4];"
                 : "=r"(r0), "=r"(r1), "=r"(r2), "=r"(r3) : "r"(addr));
}

__device__ __forceinline__ void mma_f16(float& d0, float& d1, float& d2, float& d3,
                                        uint32_t a0, uint32_t a1, uint32_t a2, uint32_t a3,
                                        uint32_t b0, uint32_t b1) {
    asm volatile(
        "mma.sync.aligned.m16n8k16.row.col.f32.f16.f16.f32 "
        "{%0,%1,%2,%3}, {%4,%5,%6,%7}, {%8,%9}, {%0,%1,%2,%3};"
        : "+f"(d0), "+f"(d1), "+f"(d2), "+f"(d3)
        : "r"(a0), "r"(a1), "r"(a2), "r"(a3), "r"(b0), "r"(b1));
}

__device__ __forceinline__ void cp16(uint32_t s, const void* g) {
    asm volatile("cp.async.cg.shared.global [%0], [%1], 16;" :: "r"(s), "l"(g) : "memory");
}
#define CP_COMMIT() asm volatile("cp.async.commit_group;" ::: "memory")
#define CP_WAIT0()  asm volatile("cp.async.wait_group 0;" ::: "memory")

// ===========================================================================
// fused conversion kernel: fp32 -> fp16 for x, w_qkv, w_out in ONE launch
// ===========================================================================
#define N_X  (Bq * Lq * Dq)          // 4194304
#define N_W  (Dq * 3 * Dq)           // 3145728
#define N_O  (Dq * Dq)               // 1048576
#define N_ALL (N_X + N_W + N_O)      // 8388608

__global__ void __launch_bounds__(256)
conv_all_fp16(const float* __restrict__ x, const float* __restrict__ w,
              const float* __restrict__ wo,
              __half* __restrict__ xh, __half* __restrict__ wh, __half* __restrict__ oh)
{
    int i = (blockIdx.x * 256 + threadIdx.x) * 4;
    const float* src;
    __half* dst;
    if (i < N_X)            { src = x  + i;              dst = xh + i; }
    else if (i < N_X + N_W) { src = w  + (i - N_X);      dst = wh + (i - N_X); }
    else                    { src = wo + (i - N_X - N_W); dst = oh + (i - N_X - N_W); }
    float4 v = *(const float4*)src;
    *(uint2*)dst = make_uint2(pack2(f16_of(v.x), f16_of(v.y)),
                              pack2(f16_of(v.z), f16_of(v.w)));
}

// ===========================================================================
// fp16 GEMM (1 mma pass). CTA 128x256, 8 warps of 64x64 (2x4), K-chunk 64,
// cp.async double-buffered, one barrier per chunk. 128 B of ldsm per mma.
// ===========================================================================
#define A_STRIDE 72          // fp16 elems per A row (144 B; 64 data + 8 pad)
#define B_STRIDE 264         // fp16 elems per B row (528 B; 256 data + 8 pad)
#define A_PLANE  (128 * A_STRIDE * 2)     // 18432 B
#define B_PLANE  (64 * B_STRIDE * 2)      // 33792 B
#define OFF_A    0
#define OFF_B    (A_PLANE)
#define BUF_BYTES (A_PLANE + B_PLANE)      // 52224
#define SMEM_GEMM_BYTES (2 * BUF_BYTES)    // 104448

template<bool OUT_F16>
__global__ void __launch_bounds__(256, 1)
gemm_f16(const __half* __restrict__ Ah, const __half* __restrict__ Bh,
         const float* __restrict__ bias, float* __restrict__ C,
         __half* __restrict__ C16, int M, int N, int K)
{
    extern __shared__ char smem[];
    const uint32_t sbase = smem_u32(smem);
    const int t    = threadIdx.x;
    const int lane = t & 31;
    const int wid  = t >> 5;
    const int warp_m = wid >> 2;      // 0..1 (64 rows each)
    const int warp_n = wid & 3;       // 0..3 (64 cols each)

    const int n0 = blockIdx.x * 256;
    const int m0 = blockIdx.y * 128;

    float acc[4][8][4];               // 128 regs
#pragma unroll
    for (int i = 0; i < 4; i++)
#pragma unroll
        for (int j = 0; j < 8; j++)
#pragma unroll
            for (int r = 0; r < 4; r++) acc[i][j][r] = 0.f;

    // cp.async loaders: A 128x64 (row=idx>>3, g=idx&7); B 64x256 (k=idx>>5, ng=idx&31)
    const int a_m0 = t >> 3, a_g = t & 7;
    const int b_k0 = t >> 5, b_ng = t & 31;

    auto issue_chunk = [&](int c) {
        const int k0 = c * 64;
        const uint32_t buf = sbase + (c & 1) * BUF_BYTES;
#pragma unroll
        for (int p = 0; p < 4; p++) {
            int m = a_m0 + p * 32;
            cp16(buf + OFF_A + m * (A_STRIDE * 2) + a_g * 16,
                 Ah + (size_t)(m0 + m) * K + k0 + a_g * 8);
        }
#pragma unroll
        for (int p = 0; p < 8; p++) {
            int k = b_k0 + p * 8;
            cp16(buf + OFF_B + k * (B_STRIDE * 2) + b_ng * 16,
                 Bh + (size_t)(k0 + k) * N + n0 + b_ng * 8);
        }
    };

    const int NCH = K / 64;
    issue_chunk(0);
    CP_COMMIT();

    for (int c = 0; c < NCH; c++) {
        CP_WAIT0();
        __syncthreads();
        if (c + 1 < NCH) {
            issue_chunk(c + 1);
            CP_COMMIT();
        }

        const uint32_t buf = sbase + (c & 1) * BUF_BYTES;
#pragma unroll
        for (int kk = 0; kk < 4; kk++) {
            const int a_row = (lane & 15);
            const int a_cb  = (lane >> 4);
            const int b_kr  = kk * 16 + (lane & 15);
            const int b_nc  = (lane & 16) ? 8 : 0;

            uint32_t af[4][4], bf[4][4];
#pragma unroll
            for (int mt = 0; mt < 4; mt++) {
                int row = warp_m * 64 + mt * 16 + a_row;
                uint32_t ad = buf + OFF_A + (row * A_STRIDE + kk * 16 + a_cb * 8) * 2;
                ldm_x4(af[mt][0], af[mt][1], af[mt][2], af[mt][3], ad);
            }
#pragma unroll
            for (int nb = 0; nb < 4; nb++) {
                int ncol = warp_n * 64 + nb * 16 + b_nc;
                uint32_t bd = buf + OFF_B + (b_kr * B_STRIDE + ncol) * 2;
                ldm_x4_t(bf[nb][0], bf[nb][1], bf[nb][2], bf[nb][3], bd);
            }
#pragma unroll
            for (int mt = 0; mt < 4; mt++)
#pragma unroll
                for (int nt = 0; nt < 8; nt++) {
                    int nb = nt >> 1, half = nt & 1;
                    mma_f16(acc[mt][nt][0], acc[mt][nt][1], acc[mt][nt][2], acc[mt][nt][3],
                            af[mt][0], af[mt][1], af[mt][2], af[mt][3],
                            bf[nb][half * 2], bf[nb][half * 2 + 1]);
                }
        }
    }

    const int r_base = m0 + warp_m * 64 + (lane >> 2);
    const int c_base = n0 + warp_n * 64 + 2 * (lane & 3);
#pragma unroll
    for (int mt = 0; mt < 4; mt++) {
#pragma unroll
        for (int nt = 0; nt < 8; nt++) {
            int col = c_base + nt * 8;
            float b0 = bias[col], b1 = bias[col + 1];
            int r0 = r_base + mt * 16;
            float v00 = acc[mt][nt][0] + b0, v01 = acc[mt][nt][1] + b1;
            float v10 = acc[mt][nt][2] + b0, v11 = acc[mt][nt][3] + b1;
            if (OUT_F16) {
                *(uint32_t*)(C16 + (size_t)r0 * N + col)       = pack2(f16_of(v00), f16_of(v01));
                *(uint32_t*)(C16 + (size_t)(r0 + 8) * N + col) = pack2(f16_of(v10), f16_of(v11));
            } else {
                *(float2*)(C + (size_t)r0 * N + col)       = make_float2(v00, v01);
                *(float2*)(C + (size_t)(r0 + 8) * N + col) = make_float2(v10, v11);
            }
        }
    }
}

// ===========================================================================
// fp16 tensor-core windowed flash attention with triangular block-skip
// (unchanged from round 16 — passing, bit-identical skip)
// ===========================================================================
#define AT_STR 144
#define OFF_K 0
#define OFF_V 18432
#define SMEM_ATT 36864

__global__ void __launch_bounds__(256, 1)
attn_flash(const __half* __restrict__ qkv, __half* __restrict__ oh_g)
{
    extern __shared__ char smem[];
    const uint32_t sb = smem_u32(smem);
    const int qt = blockIdx.x, h = blockIdx.y, b = blockIdx.z;
    const int t = threadIdx.x, lane = t & 31, wid = t >> 5;

#pragma unroll
    for (int p = 0; p < 4; p++) {
        int idx = t + p * 256;
        int row = idx >> 3, g = idx & 7;
        const __half* src = qkv
            + ((size_t)(b * Lq + qt * QT + row) * 3 + 0) * Dq + h * HDq + g * 8;
        uint4 v = *(const uint4*)src;
        uint32_t dst = sb + OFF_K + row * AT_STR + g * 16;
        asm volatile("st.shared.v4.b32 [%0], {%1,%2,%3,%4};" ::
                     "r"(dst), "r"(v.x), "r"(v.y), "r"(v.z), "r"(v.w) : "memory");
    }
    __syncthreads();

    uint32_t qf[4][4];
    {
        int a_row = lane & 15, a_cb = lane >> 4;
        int qrow = wid * 16 + a_row;
#pragma unroll
        for (int ks = 0; ks < 4; ks++) {
            uint32_t ad = sb + OFF_K + qrow * AT_STR + (ks * 16 + a_cb * 8) * 2;
            ldm_x4(qf[ks][0], qf[ks][1], qf[ks][2], qf[ks][3], ad);
        }
    }

    float o[8][4];
#pragma unroll
    for (int i = 0; i < 8; i++)
#pragma unroll
        for (int r = 0; r < 4; r++) o[i][r] = 0.f;
    float ls0 = 0.f, ls1 = 0.f;

    const int i_lo = wid * 16 + (lane >> 2);
    const int i_hi = i_lo + 8;
    const int jj_b = (lane & 3) * 2;

    const int bn_row = (lane & 7) + ((lane & 16) >> 1);
    const int bk_off = (lane & 8);
    const int v_kr = (lane & 15);
    const int v_nc = (lane & 16) ? 8 : 0;

    for (int ch = 0; ch < 3; ch++) {
        if (ch == 0 && qt == 0) continue;
        if (ch == 2 && qt == (Lq / QT) - 1) continue;
        const int jbase = qt * QT + (ch - 1) * 128;

        __syncthreads();
#pragma unroll
        for (int p = 0; p < 8; p++) {
            int idx = t + p * 256;
            int plane = idx >> 10, rem = idx & 1023, row = rem >> 3, g = rem & 7;
            int which = plane + 1;     // 1 = K, 2 = V
            const __half* src = qkv
                + ((size_t)(b * Lq + jbase + row) * 3 + which) * Dq + h * HDq + g * 8;
            uint4 v = *(const uint4*)src;
            uint32_t off = plane ? OFF_V : OFF_K;
            uint32_t dst = sb + off + row * AT_STR + g * 16;
            asm volatile("st.shared.v4.b32 [%0], {%1,%2,%3,%4};" ::
                         "r"(dst), "r"(v.x), "r"(v.y), "r"(v.z), "r"(v.w) : "memory");
        }
        __syncthreads();

        float sacc[16][4];
#pragma unroll
        for (int i = 0; i < 16; i++)
#pragma unroll
            for (int r = 0; r < 4; r++) sacc[i][r] = 0.f;

#pragma unroll
        for (int ng = 0; ng < 8; ng++) {
            if (ch == 0 && ng < wid) continue;
            if (ch == 2 && ng > wid) continue;
#pragma unroll
            for (int ks = 0; ks < 4; ks++) {
                uint32_t k0, k1, k2, k3;
                uint32_t ad = sb + OFF_K + (ng * 16 + bn_row) * AT_STR + (ks * 16 + bk_off) * 2;
                ldm_x4(k0, k1, k2, k3, ad);
                int n0 = ng * 2, n1 = ng * 2 + 1;
                mma_f16(sacc[n0][0], sacc[n0][1], sacc[n0][2], sacc[n0][3],
                        qf[ks][0], qf[ks][1], qf[ks][2], qf[ks][3], k0, k1);
                mma_f16(sacc[n1][0], sacc[n1][1], sacc[n1][2], sacc[n1][3],
                        qf[ks][0], qf[ks][1], qf[ks][2], qf[ks][3], k2, k3);
            }
        }

        uint32_t pp[16][2];
#pragma unroll
        for (int nt = 0; nt < 16; nt++) {
            if (ch == 0 && nt < 2 * wid) continue;
            if (ch == 2 && nt >= 2 * wid + 2) continue;
            int jj0 = nt * 8 + jj_b, jj1 = jj0 + 1;
            float p0 = __expf(sacc[nt][0] * 0.125f);
            float p1 = __expf(sacc[nt][1] * 0.125f);
            float p2 = __expf(sacc[nt][2] * 0.125f);
            float p3 = __expf(sacc[nt][3] * 0.125f);
            if (ch == 0) {
                if (jj0 < i_lo) p0 = 0.f;
                if (jj1 < i_lo) p1 = 0.f;
                if (jj0 < i_hi) p2 = 0.f;
                if (jj1 < i_hi) p3 = 0.f;
            } else if (ch == 2) {
                if (jj0 > i_lo) p0 = 0.f;
                if (jj1 > i_lo) p1 = 0.f;
                if (jj0 > i_hi) p2 = 0.f;
                if (jj1 > i_hi) p3 = 0.f;
            }
            ls0 += p0 + p1;
            ls1 += p2 + p3;
            pp[nt][0] = f16x2_of(p0, p1);
            pp[nt][1] = f16x2_of(p2, p3);
        }

#pragma unroll
        for (int ks = 0; ks < 8; ks++) {
            if (ch == 0 && ks < wid) continue;
            if (ch == 2 && ks > wid) continue;
            uint32_t a0 = pp[2 * ks][0], a1 = pp[2 * ks][1];
            uint32_t a2 = pp[2 * ks + 1][0], a3 = pp[2 * ks + 1][1];
#pragma unroll
            for (int ng = 0; ng < 4; ng++) {
                uint32_t v0, v1, v2, v3;
                uint32_t ad = sb + OFF_V + (ks * 16 + v_kr) * AT_STR + (ng * 16 + v_nc) * 2;
                ldm_x4_t(v0, v1, v2, v3, ad);
                int d0 = ng * 2, d1 = ng * 2 + 1;
                mma_f16(o[d0][0], o[d0][1], o[d0][2], o[d0][3], a0, a1, a2, a3, v0, v1);
                mma_f16(o[d1][0], o[d1][1], o[d1][2], o[d1][3], a0, a1, a2, a3, v2, v3);
            }
        }
    }

    ls0 += __shfl_xor_sync(0xffffffffu, ls0, 1);
    ls0 += __shfl_xor_sync(0xffffffffu, ls0, 2);
    ls1 += __shfl_xor_sync(0xffffffffu, ls1, 1);
    ls1 += __shfl_xor_sync(0xffffffffu, ls1, 2);
    float inv0 = 1.f / ls0, inv1 = 1.f / ls1;

    const int qg0 = qt * QT + i_lo;
#pragma unroll
    for (int dt = 0; dt < 8; dt++) {
        int d = h * HDq + dt * 8 + jj_b;
        size_t base0 = (size_t)(b * Lq + qg0) * Dq + d;
        size_t base1 = base0 + (size_t)8 * Dq;
        *(uint32_t*)(oh_g + base0) = pack2(f16_of(o[dt][0] * inv0), f16_of(o[dt][1] * inv0));
        *(uint32_t*)(oh_g + base1) = pack2(f16_of(o[dt][2] * inv1), f16_of(o[dt][3] * inv1));
    }
}

// ---------------------------------------------------------------------------
extern "C" void kernel_launch(void* const* d_in, const int* in_sizes, int n_in,
                              void* d_out, int out_size)
{
    const float* x     = (const float*)d_in[0];
    const float* w_qkv = (const float*)d_in[1];
    const float* b_qkv = (const float*)d_in[2];
    const float* w_out = (const float*)d_in[3];
    const float* b_out = (const float*)d_in[4];
    float* out = (float*)d_out;

    __half *qkv16, *xh, *wh, *oh, *ah;
    cudaGetSymbolAddress((void**)&qkv16, g_qkv16);
    cudaGetSymbolAddress((void**)&xh, g_x_h);
    cudaGetSymbolAddress((void**)&wh, g_wqkv_h);
    cudaGetSymbolAddress((void**)&oh, g_wout_h);
    cudaGetSymbolAddress((void**)&ah, g_attn_h);

    const int M = Bq * Lq;    // 4096

    cudaFuncSetAttribute(gemm_f16<true>,  cudaFuncAttributeMaxDynamicSharedMemorySize, SMEM_GEMM_BYTES);
    cudaFuncSetAttribute(gemm_f16<false>, cudaFuncAttributeMaxDynamicSharedMemorySize, SMEM_GEMM_BYTES);
    cudaFuncSetAttribute(attn_flash, cudaFuncAttributeMaxDynamicSharedMemorySize, SMEM_ATT);

    // 0) fused conversion to fp16 (single launch)
    conv_all_fp16<<<N_ALL / 1024, 256>>>(x, w_qkv, w_out, xh, wh, oh);

    // 1) QKV projection -> single fp16 plane
    {
        dim3 grid(3 * Dq / 256, M / 128);   // 12 x 32
        gemm_f16<true><<<grid, 256, SMEM_GEMM_BYTES>>>(
            xh, wh, b_qkv, nullptr, qkv16, M, 3 * Dq, Dq);
    }

    // 2) fp16 tensor-core windowed attention
    {
        dim3 grid(Lq / QT, Hq, Bq);
        attn_flash<<<grid, 256, SMEM_ATT>>>(qkv16, ah);
    }

    // 3) Output projection -> fp32 out
    {
        dim3 grid(Dq / 256, M / 128);       // 4 x 32
        gemm_f16<false><<<grid, 256, SMEM_GEMM_BYTES>>>(
            ah, oh, b_out, out, nullptr, M, Dq, Dq);
    }
}